// round 9
// baseline (speedup 1.0000x reference)
#include <cuda_runtime.h>
#include <cuda_bf16.h>
#include <math.h>
#include <stdint.h>

#define S_TOK   1024
#define DIM     2560
#define HD      128
#define NH      20
#define NKV     5
#define QKV_OUT 3840
#define KW      640      // K in int32 words (2560/4)
#define NGRP    20       // scale groups (2560/128)

// ---------------- device scratch (static, no allocation) ----------------
__device__ int    g_wq[QKV_OUT * KW];
__device__ int    g_wo[DIM * KW];
__device__ int    g_qx[S_TOK * KW];
__device__ float  g_sx[S_TOK];
__device__ float  g_qkv[S_TOK * QKV_OUT];
__device__ float  g_qf[S_TOK * NH * HD];
__device__ float  g_kf[S_TOK * NKV * HD];
__device__ float  g_vf[S_TOK * NKV * HD];
__device__ float  g_attn[S_TOK * NH * HD];
__device__ int    g_qa[S_TOK * KW];
__device__ float  g_sa[S_TOK];
__device__ float2 g_rope[S_TOK * 64];

// ---------------- f32x2 helpers ----------------
__device__ __forceinline__ void fma2(unsigned long long& d, unsigned long long a,
                                     unsigned long long b) {
    asm("fma.rn.f32x2 %0, %1, %2, %3;" : "=l"(d) : "l"(a), "l"(b), "l"(d));
}
__device__ __forceinline__ unsigned long long mul2(unsigned long long a,
                                                   unsigned long long b) {
    unsigned long long d;
    asm("mul.rn.f32x2 %0, %1, %2;" : "=l"(d) : "l"(a), "l"(b));
    return d;
}
__device__ __forceinline__ unsigned long long pk2(float lo, float hi) {
    unsigned long long r;
    asm("mov.b64 %0, {%1, %2};" : "=l"(r) : "r"(__float_as_uint(lo)), "r"(__float_as_uint(hi)));
    return r;
}
__device__ __forceinline__ float2 upk2(unsigned long long v) {
    unsigned lo, hi;
    asm("mov.b64 {%0, %1}, %2;" : "=r"(lo), "=r"(hi) : "l"(v));
    return make_float2(__uint_as_float(lo), __uint_as_float(hi));
}

// ---------------- cp.async helpers ----------------
#define CP16(dst, src)                                                          \
    do {                                                                        \
        unsigned _sa = (unsigned)__cvta_generic_to_shared(dst);                 \
        asm volatile("cp.async.cg.shared.global [%0], [%1], 16;" ::"r"(_sa),    \
                     "l"(src));                                                 \
    } while (0)
#define CPCOMMIT() asm volatile("cp.async.commit_group;")
#define CPWAIT1()  asm volatile("cp.async.wait_group 1;")
#define CPWAIT0()  asm volatile("cp.async.wait_group 0;")

// ---------------- int8 mma.sync (baseline PTX, tensor pipe) ----------------
__device__ __forceinline__ void mma_s8(int& c0, int& c1, int& c2, int& c3,
                                       int a0, int a1, int a2, int a3,
                                       int b0, int b1) {
    asm volatile(
        "mma.sync.aligned.m16n8k32.row.col.s32.s8.s8.s32 "
        "{%0,%1,%2,%3}, {%4,%5,%6,%7}, {%8,%9}, {%0,%1,%2,%3};"
        : "+r"(c0), "+r"(c1), "+r"(c2), "+r"(c3)
        : "r"(a0), "r"(a1), "r"(a2), "r"(a3), "r"(b0), "r"(b1));
}

// ---------------- ternary weight f32 -> packed int8 (vectorized) ----------------
__global__ void conv_w_kernel(const float* __restrict__ w, int rows, int which) {
    int* dst = which ? g_wo : g_wq;
    int total = rows * KW;
    for (int i = blockIdx.x * blockDim.x + threadIdx.x; i < total;
         i += gridDim.x * blockDim.x) {
        float4 v = *(const float4*)&w[(size_t)i * 4];
        int b0 = (int)v.x, b1 = (int)v.y, b2 = (int)v.z, b3 = (int)v.w;
        dst[i] = (b0 & 0xFF) | ((b1 & 0xFF) << 8) | ((b2 & 0xFF) << 16) | ((b3 & 0xFF) << 24);
    }
}

// ---------------- RoPE table (double precision, tiny) ----------------
__global__ void rope_kernel() {
    int idx = blockIdx.x * 256 + threadIdx.x;   // 65536 total
    int t = idx >> 6, p = idx & 63;
    double inv = exp(-(double)p / 64.0 * log(500000.0));
    double ang = (double)t * inv;
    g_rope[idx] = make_float2((float)cos(ang), (float)sin(ang));
}

// ---------------- per-token activation quant (vectorized) ----------------
__global__ void quant_kernel(const float* __restrict__ xsrc, int which) {
    int t = blockIdx.x;
    const float4* row = which ? (const float4*)&g_attn[t * DIM]
                              : (const float4*)(xsrc + (size_t)t * DIM);
    __shared__ float red[8];
    float m = 0.f;
    for (int i = threadIdx.x; i < KW; i += 256) {
        float4 v = row[i];
        m = fmaxf(m, fmaxf(fmaxf(fabsf(v.x), fabsf(v.y)), fmaxf(fabsf(v.z), fabsf(v.w))));
    }
    #pragma unroll
    for (int o = 16; o; o >>= 1) m = fmaxf(m, __shfl_xor_sync(0xffffffffu, m, o));
    if ((threadIdx.x & 31) == 0) red[threadIdx.x >> 5] = m;
    __syncthreads();
    if (threadIdx.x < 8) {
        m = red[threadIdx.x];
        #pragma unroll
        for (int o = 4; o; o >>= 1) m = fmaxf(m, __shfl_xor_sync(0xffu, m, o));
        if (threadIdx.x == 0) red[0] = m;
    }
    __syncthreads();
    m = fmaxf(red[0], 1e-5f);
    float s = 127.f / m;
    if (threadIdx.x == 0) { if (which) g_sa[t] = s; else g_sx[t] = s; }
    int* q = (which ? g_qa : g_qx) + t * KW;
    for (int w = threadIdx.x; w < KW; w += 256) {
        float4 v = row[w];
        int q0 = min(127, max(-128, (int)rintf(v.x * s)));
        int q1 = min(127, max(-128, (int)rintf(v.y * s)));
        int q2 = min(127, max(-128, (int)rintf(v.z * s)));
        int q3 = min(127, max(-128, (int)rintf(v.w * s)));
        q[w] = (q0 & 0xFF) | ((q1 & 0xFF) << 8) | ((q2 & 0xFF) << 16) | ((q3 & 0xFF) << 24);
    }
}

// ---------------- mma.sync int8 group-scaled GEMM (unchanged from R6) ----------------
#define ASTRIDE 144
#define A_BUF   (128 * ASTRIDE)
#define B_BUF   (64 * ASTRIDE)
#define WS_OFF  0
#define SV_OFF  (64 * NGRP * 4)
#define A_OFF   (SV_OFF + 512)
#define B_OFF   (A_OFF + 2 * A_BUF)
#define GEMM_SMEM (B_OFF + 2 * B_BUF)

__global__ __launch_bounds__(256, 1) void gemm_mma_kernel(int which,
                                                          const float* __restrict__ ws,
                                                          float* __restrict__ dOut, int N) {
    const int* __restrict__ Aq = which ? g_qa : g_qx;
    const int* __restrict__ Bw = which ? g_wo : g_wq;
    const float* __restrict__ sv = which ? g_sa : g_sx;
    float* __restrict__ C = which ? dOut : g_qkv;

    extern __shared__ char sm[];
    float* ws_s = (float*)(sm + WS_OFF);   // [g][col] 20x64
    float* sv_s = (float*)(sm + SV_OFF);   // 128

    const int tid = threadIdx.x, wid = tid >> 5, lane = tid & 31;
    const int g4 = lane >> 2, tig = lane & 3;
    const int warpM = (wid & 3) * 32, warpN = (wid >> 2) * 32;
    const int rowBase = blockIdx.y * 128, colBase = blockIdx.x * 64;

    for (int i = tid; i < 64 * NGRP; i += 256) {
        int c = i / NGRP, g = i - c * NGRP;
        ws_s[g * 64 + c] = ws[(size_t)(colBase + c) * NGRP + g];
    }
    if (tid < 128) sv_s[tid] = sv[rowBase + tid];

    const int* Abase = Aq + (size_t)rowBase * KW;
    const int* Bbase = Bw + (size_t)colBase * KW;

    auto issue = [&](int g, int b) {
        #pragma unroll
        for (int u = 0; u < 4; u++) {
            int c = tid + 256 * u;
            int r = c >> 3, c16 = c & 7;
            CP16(sm + A_OFF + b * A_BUF + r * ASTRIDE + c16 * 16,
                 Abase + r * KW + g * 32 + c16 * 4);
        }
        #pragma unroll
        for (int u = 0; u < 2; u++) {
            int c = tid + 256 * u;
            int r = c >> 3, c16 = c & 7;
            CP16(sm + B_OFF + b * B_BUF + r * ASTRIDE + c16 * 16,
                 Bbase + r * KW + g * 32 + c16 * 4);
        }
        CPCOMMIT();
    };

    float facc[2][4][4];
    #pragma unroll
    for (int mt = 0; mt < 2; mt++)
        #pragma unroll
        for (int nt = 0; nt < 4; nt++)
            #pragma unroll
            for (int k = 0; k < 4; k++) facc[mt][nt][k] = 0.f;

    issue(0, 0);

    for (int g = 0; g < NGRP; g++) {
        int b = g & 1;
        if (g + 1 < NGRP) { issue(g + 1, b ^ 1); CPWAIT1(); } else { CPWAIT0(); }
        __syncthreads();

        const char* smA = sm + A_OFF + b * A_BUF;
        const char* smB = sm + B_OFF + b * B_BUF;
        int acc[2][4][4] = {};
        #pragma unroll
        for (int ks = 0; ks < 4; ks++) {
            int kb = ks * 32 + tig * 4;
            int a[2][4], bb[4][2];
            #pragma unroll
            for (int mt = 0; mt < 2; mt++) {
                int ra = warpM + mt * 16 + g4;
                a[mt][0] = *(const int*)(smA + ra * ASTRIDE + kb);
                a[mt][1] = *(const int*)(smA + (ra + 8) * ASTRIDE + kb);
                a[mt][2] = *(const int*)(smA + ra * ASTRIDE + kb + 16);
                a[mt][3] = *(const int*)(smA + (ra + 8) * ASTRIDE + kb + 16);
            }
            #pragma unroll
            for (int nt = 0; nt < 4; nt++) {
                int cn = warpN + nt * 8 + g4;
                bb[nt][0] = *(const int*)(smB + cn * ASTRIDE + kb);
                bb[nt][1] = *(const int*)(smB + cn * ASTRIDE + kb + 16);
            }
            #pragma unroll
            for (int mt = 0; mt < 2; mt++)
                #pragma unroll
                for (int nt = 0; nt < 4; nt++)
                    mma_s8(acc[mt][nt][0], acc[mt][nt][1], acc[mt][nt][2], acc[mt][nt][3],
                           a[mt][0], a[mt][1], a[mt][2], a[mt][3], bb[nt][0], bb[nt][1]);
        }
        #pragma unroll
        for (int nt = 0; nt < 4; nt++) {
            float2 w2 = *(const float2*)&ws_s[g * 64 + warpN + nt * 8 + tig * 2];
            #pragma unroll
            for (int mt = 0; mt < 2; mt++) {
                facc[mt][nt][0] += (float)acc[mt][nt][0] * w2.x;
                facc[mt][nt][1] += (float)acc[mt][nt][1] * w2.y;
                facc[mt][nt][2] += (float)acc[mt][nt][2] * w2.x;
                facc[mt][nt][3] += (float)acc[mt][nt][3] * w2.y;
            }
        }
        __syncthreads();
    }

    #pragma unroll
    for (int mt = 0; mt < 2; mt++) {
        int r0 = warpM + mt * 16 + g4, r1 = r0 + 8;
        float inv0 = 1.f / sv_s[r0], inv1 = 1.f / sv_s[r1];
        #pragma unroll
        for (int nt = 0; nt < 4; nt++) {
            int col = colBase + warpN + nt * 8 + tig * 2;
            *(float2*)&C[(size_t)(rowBase + r0) * N + col] =
                make_float2(facc[mt][nt][0] * inv0, facc[mt][nt][1] * inv0);
            *(float2*)&C[(size_t)(rowBase + r1) * N + col] =
                make_float2(facc[mt][nt][2] * inv1, facc[mt][nt][3] * inv1);
        }
    }
}

// ---------------- RMSNorm + RoPE (+ V copy), table-based ----------------
__global__ void post_kernel(const float* __restrict__ qnw, const float* __restrict__ knw) {
    int t = blockIdx.x, u = blockIdx.y, d = threadIdx.x;   // 128 threads
    const float* src;
    float* dst;
    const float* nw;
    if (u < NH) {
        src = &g_qkv[t * QKV_OUT + u * HD];
        dst = &g_qf[(t * NH + u) * HD];
        nw = qnw;
    } else if (u < NH + NKV) {
        int kv = u - NH;
        src = &g_qkv[t * QKV_OUT + NH * HD + kv * HD];
        dst = &g_kf[(t * NKV + kv) * HD];
        nw = knw;
    } else {
        int kv = u - NH - NKV;
        g_vf[(t * NKV + kv) * HD + d] = g_qkv[t * QKV_OUT + (NH + NKV) * HD + kv * HD + d];
        return;
    }
    __shared__ float buf[HD];
    __shared__ float red[4];
    float v = src[d];
    float sq = v * v;
    #pragma unroll
    for (int o = 16; o; o >>= 1) sq += __shfl_xor_sync(0xffffffffu, sq, o);
    if ((d & 31) == 0) red[d >> 5] = sq;
    __syncthreads();
    float mean = (red[0] + red[1] + red[2] + red[3]) * (1.f / 128.f);
    float r = rsqrtf(mean + 1e-5f);
    buf[d] = v * r * nw[d];
    __syncthreads();
    int p = d >> 1;
    float2 cs = g_rope[t * 64 + p];
    float x0 = buf[p * 2], x1 = buf[p * 2 + 1];
    dst[d] = (d & 1) ? (x0 * cs.y + x1 * cs.x) : (x0 * cs.x - x1 * cs.y);
}

// ---------------- causal GQA flash attention (fp32, f32x2 FMA) ----------------
// 32-row Q tiles, 64-row K/V tiles, 2 CTAs/SM, long-tiles-first schedule.
#define SWZ(r, ch) ((r) * 32 + ((ch) ^ ((r) & 31)))
#define SMEM_ATTN ((1024 + 2048 + 2048) * 16 + 32 * 68 * 4)

__global__ __launch_bounds__(256, 2) void attn_kernel() {
    extern __shared__ float4 smv[];
    float4* Qc = smv;            // 32 rows x 32 chunks (swizzled)
    float4* Kc = Qc + 1024;      // 64 rows x 32 chunks
    float4* Vc = Kc + 2048;      // 64 rows x 32 chunks
    float* Ps = (float*)(Vc + 2048);   // 32 x 68

    const int flat = blockIdx.x;
    const int qt = 31 - flat / NH;     // descending: heavy tiles first
    const int hh = flat % NH;
    const int g = hh >> 2;
    const int tid = threadIdx.x;
    const int tx = tid & 15, ty = tid >> 4;   // rows ty*2+i, cols tx*4+j
    const float scale = 0.08838834764831845f; // 128^-0.5

    // load Q tile prescaled (swizzled float4)
    for (int i = tid; i < 1024; i += 256) {
        int r = i >> 5, ch = i & 31;
        float4 q = *(const float4*)&g_qf[((size_t)(qt * 32 + r) * NH + hh) * HD + ch * 4];
        q.x *= scale; q.y *= scale; q.z *= scale; q.w *= scale;
        Qc[SWZ(r, ch)] = q;
    }

    float m_i[2], l_i[2];
    unsigned long long o2[2][4];
    #pragma unroll
    for (int i = 0; i < 2; i++) {
        m_i[i] = -1e30f; l_i[i] = 0.f;
        #pragma unroll
        for (int k = 0; k < 4; k++) o2[i][k] = 0ull;
    }
    __syncthreads();

    const int ktMax = qt >> 1;   // last K tile containing the diagonal
    for (int kt = 0; kt <= ktMax; kt++) {
        for (int i = tid; i < 2048; i += 256) {
            int r = i >> 5, ch = i & 31;
            Kc[SWZ(r, ch)] = *(const float4*)&g_kf[((size_t)(kt * 64 + r) * NKV + g) * HD + ch * 4];
            Vc[SWZ(r, ch)] = *(const float4*)&g_vf[((size_t)(kt * 64 + r) * NKV + g) * HD + ch * 4];
        }
        __syncthreads();

        // scores via packed f32x2: rows ty*2+i, cols tx*4+j
        unsigned long long s2[2][4];
        #pragma unroll
        for (int i = 0; i < 2; i++)
            #pragma unroll
            for (int j = 0; j < 4; j++) s2[i][j] = 0ull;
        #pragma unroll 4
        for (int ch = 0; ch < 32; ch++) {
            ulonglong2 q4[2], k4[4];
            #pragma unroll
            for (int i = 0; i < 2; i++) q4[i] = *(const ulonglong2*)&Qc[SWZ(ty * 2 + i, ch)];
            #pragma unroll
            for (int j = 0; j < 4; j++) k4[j] = *(const ulonglong2*)&Kc[SWZ(tx * 4 + j, ch)];
            #pragma unroll
            for (int i = 0; i < 2; i++)
                #pragma unroll
                for (int j = 0; j < 4; j++) {
                    fma2(s2[i][j], q4[i].x, k4[j].x);
                    fma2(s2[i][j], q4[i].y, k4[j].y);
                }
        }

        // fused online softmax: 16 threads (same ty) own each row
        float corr[2];
        #pragma unroll
        for (int i = 0; i < 2; i++) {
            int rg = qt * 32 + ty * 2 + i;
            float s[4];
            #pragma unroll
            for (int j = 0; j < 4; j++) {
                float2 t2 = upk2(s2[i][j]);
                float v = t2.x + t2.y;
                s[j] = (kt * 64 + tx * 4 + j <= rg) ? v : -1e30f;
            }
            float mt = fmaxf(fmaxf(s[0], s[1]), fmaxf(s[2], s[3]));
            #pragma unroll
            for (int o = 1; o < 16; o <<= 1) mt = fmaxf(mt, __shfl_xor_sync(0xffffffffu, mt, o, 16));
            float mn = fmaxf(m_i[i], mt);
            float p0 = expf(s[0] - mn), p1 = expf(s[1] - mn);
            float p2v = expf(s[2] - mn), p3 = expf(s[3] - mn);
            *(float4*)&Ps[(ty * 2 + i) * 68 + tx * 4] = make_float4(p0, p1, p2v, p3);
            float lt = (p0 + p1) + (p2v + p3);
            #pragma unroll
            for (int o = 1; o < 16; o <<= 1) lt += __shfl_xor_sync(0xffffffffu, lt, o, 16);
            corr[i] = expf(m_i[i] - mn);
            l_i[i] = l_i[i] * corr[i] + lt;
            m_i[i] = mn;
        }
        __syncthreads();

        // rescale + P @ V : rows ty*2+i, dims tx*8..tx*8+7 (packed pairs)
        #pragma unroll
        for (int i = 0; i < 2; i++) {
            unsigned long long c2 = pk2(corr[i], corr[i]);
            #pragma unroll
            for (int k = 0; k < 4; k++) o2[i][k] = mul2(o2[i][k], c2);
        }
        #pragma unroll 4
        for (int j = 0; j < 64; j++) {
            ulonglong2 va = *(const ulonglong2*)&Vc[j * 32 + ((2 * tx) ^ (j & 31))];
            ulonglong2 vb = *(const ulonglong2*)&Vc[j * 32 + ((2 * tx + 1) ^ (j & 31))];
            #pragma unroll
            for (int i = 0; i < 2; i++) {
                float p = Ps[(ty * 2 + i) * 68 + j];
                unsigned long long pp = pk2(p, p);
                fma2(o2[i][0], pp, va.x);
                fma2(o2[i][1], pp, va.y);
                fma2(o2[i][2], pp, vb.x);
                fma2(o2[i][3], pp, vb.y);
            }
        }
        __syncthreads();
    }

    #pragma unroll
    for (int i = 0; i < 2; i++) {
        float inv = 1.f / l_i[i];
        float2 a0 = upk2(o2[i][0]), a1 = upk2(o2[i][1]);
        float2 b0 = upk2(o2[i][2]), b1 = upk2(o2[i][3]);
        float* dst = &g_attn[(size_t)(qt * 32 + ty * 2 + i) * DIM + hh * HD + tx * 8];
        *(float4*)dst = make_float4(a0.x * inv, a0.y * inv, a1.x * inv, a1.y * inv);
        *(float4*)(dst + 4) = make_float4(b0.x * inv, b0.y * inv, b1.x * inv, b1.y * inv);
    }
}

// ---------------- launch ----------------
extern "C" void kernel_launch(void* const* d_in, const int* in_sizes, int n_in,
                              void* d_out, int out_size) {
    const float* x      = (const float*)d_in[0];
    const float* w_qkv  = (const float*)d_in[1];
    const float* ws_qkv = (const float*)d_in[2];
    const float* w_o    = (const float*)d_in[3];
    const float* ws_o   = (const float*)d_in[4];
    const float* qnw    = (const float*)d_in[5];
    const float* knw    = (const float*)d_in[6];
    float* out = (float*)d_out;

    cudaFuncSetAttribute(attn_kernel, cudaFuncAttributeMaxDynamicSharedMemorySize, SMEM_ATTN);
    cudaFuncSetAttribute(gemm_mma_kernel, cudaFuncAttributeMaxDynamicSharedMemorySize, GEMM_SMEM);

    conv_w_kernel<<<2048, 256>>>(w_qkv, QKV_OUT, 0);
    conv_w_kernel<<<2048, 256>>>(w_o, DIM, 1);
    rope_kernel<<<256, 256>>>();
    quant_kernel<<<S_TOK, 256>>>(x, 0);
    gemm_mma_kernel<<<dim3(QKV_OUT / 64, S_TOK / 128), 256, GEMM_SMEM>>>(0, ws_qkv, nullptr, QKV_OUT);
    post_kernel<<<dim3(S_TOK, NH + 2 * NKV), 128>>>(qnw, knw);
    attn_kernel<<<32 * NH, 256, SMEM_ATTN>>>();
    quant_kernel<<<S_TOK, 256>>>(nullptr, 1);
    gemm_mma_kernel<<<dim3(DIM / 64, S_TOK / 128), 256, GEMM_SMEM>>>(1, ws_o, out, DIM);
}